// round 15
// baseline (speedup 1.0000x reference)
#include <cuda_runtime.h>

#define RESN  320
#define BATCH 32
#define HW    (RESN*RESN)

#define RPITCH 321   // float2 pitch for natural-order rows
#define ZPITCH 337   // float2 pitch for z-buffer rows

// Scratch (allocation-free rule: __device__ globals)
__device__ float2 g_tmp[BATCH*HW];   // intermediate after row FFTs, transposed

// ---------------------------------------------------------------------------
// complex helpers
// ---------------------------------------------------------------------------
__device__ __forceinline__ float2 cadd(float2 a, float2 b){ return make_float2(a.x+b.x, a.y+b.y); }
__device__ __forceinline__ float2 csub(float2 a, float2 b){ return make_float2(a.x-b.x, a.y-b.y); }
__device__ __forceinline__ float2 cmul(float2 a, float2 b){
    return make_float2(a.x*b.x - a.y*b.y, a.x*b.y + a.y*b.x);
}
__device__ __forceinline__ float2 cjmul(float2 a){ return make_float2(-a.y, a.x); } // i*a

// ===========================================================================
// Register FFT (20x16 decomposition): radices 5,4 (phase A) then 4,4 (phase B)
// ===========================================================================
__constant__ float2 cW20[13] = {   // exp(i*pi*j/10)
    { 1.f, 0.f},
    { 0.95105651629515353f, 0.30901699437494742f},
    { 0.80901699437494745f, 0.58778525229247314f},
    { 0.58778525229247314f, 0.80901699437494745f},
    { 0.30901699437494742f, 0.95105651629515353f},
    { 0.f, 1.f},
    {-0.30901699437494742f, 0.95105651629515353f},
    {-0.58778525229247314f, 0.80901699437494745f},
    {-0.80901699437494745f, 0.58778525229247314f},
    {-0.95105651629515353f, 0.30901699437494742f},
    {-1.f, 0.f},
    {-0.95105651629515353f, -0.30901699437494742f},
    {-0.80901699437494745f, -0.58778525229247314f}
};
__constant__ float2 cC20[4] = {    // exp(i*pi*w/8)
    {1.f,0.f},
    {0.92387953251128674f, 0.38268343236508978f},
    {0.70710678118654757f, 0.70710678118654757f},
    {0.38268343236508978f, 0.92387953251128674f}
};
__constant__ float2 cD40[4] = {    // exp(i*pi*w/4)
    {1.f,0.f},
    {0.70710678118654757f, 0.70710678118654757f},
    {0.f,1.f},
    {-0.70710678118654757f, 0.70710678118654757f}
};
__constant__ float2 cE60[4] = {    // exp(i*3*pi*w/8)
    {1.f,0.f},
    {0.38268343236508978f, 0.92387953251128674f},
    {-0.70710678118654757f, 0.70710678118654757f},
    {-0.92387953251128674f, -0.38268343236508978f}
};

__device__ __forceinline__ void radix5_bf(float2 v0, float2 v1, float2 v2, float2 v3, float2 v4,
                                          float2& o0, float2& o1, float2& o2, float2& o3, float2& o4)
{
    const float c1 =  0.30901699437494745f, c2 = -0.80901699437494745f;
    const float s1 =  0.95105651629515353f, s2 =  0.58778525229247314f;
    float2 t1 = cadd(v1, v4), t2 = cadd(v2, v3);
    float2 t3 = csub(v1, v4), t4 = csub(v2, v3);
    float2 a1 = make_float2(v0.x + c1*t1.x + c2*t2.x, v0.y + c1*t1.y + c2*t2.y);
    float2 a2 = make_float2(v0.x + c2*t1.x + c1*t2.x, v0.y + c2*t1.y + c1*t2.y);
    float2 b1 = make_float2(s1*t3.x + s2*t4.x, s1*t3.y + s2*t4.y);
    float2 b2 = make_float2(s2*t3.x - s1*t4.x, s2*t3.y - s1*t4.y);
    float2 ib1 = cjmul(b1), ib2 = cjmul(b2);
    o0 = make_float2(v0.x + t1.x + t2.x, v0.y + t1.y + t2.y);
    o1 = cadd(a1, ib1);
    o2 = cadd(a2, ib2);
    o3 = csub(a2, ib2);
    o4 = csub(a1, ib1);
}

__device__ __forceinline__ void radix4_bf(float2 v0, float2 v1, float2 v2, float2 v3,
                                          float2 w1, float2 w2, float2 w3,
                                          float2& o0, float2& o1, float2& o2, float2& o3)
{
    v1 = cmul(v1, w1); v2 = cmul(v2, w2); v3 = cmul(v3, w3);
    float2 t0 = cadd(v0, v2), t1 = csub(v0, v2);
    float2 t2 = cadd(v1, v3), t3 = csub(v1, v3);
    float2 it3 = cjmul(t3);
    o0 = cadd(t0, t2); o1 = cadd(t1, it3); o2 = csub(t0, t2); o3 = csub(t1, it3);
}

// Phase A: radix-5 then radix-4 (Ns=1, Ns=5) in registers; thread g = 0..15.
__device__ __forceinline__ void fft_phaseA(const float2* __restrict__ src,
                                           float2* __restrict__ zbuf, int g)
{
    float2 f[4][5];
    #pragma unroll
    for (int k = 0; k < 4; ++k) {
        float2 e0 = src[g + 16*k];
        float2 e1 = src[g + 16*k + 64];
        float2 e2 = src[g + 16*k + 128];
        float2 e3 = src[g + 16*k + 192];
        float2 e4 = src[g + 16*k + 256];
        radix5_bf(e0, e1, e2, e3, e4,
                  f[k][0], f[k][1], f[k][2], f[k][3], f[k][4]);
    }
    #pragma unroll
    for (int p = 0; p < 5; ++p) {
        float2 o0, o1, o2, o3;
        radix4_bf(f[0][p], f[1][p], f[2][p], f[3][p],
                  cW20[p], cW20[2*p], cW20[3*p], o0, o1, o2, o3);
        zbuf[21*g + p]      = o0;
        zbuf[21*g + 5 + p]  = o1;
        zbuf[21*g + 10 + p] = o2;
        zbuf[21*g + 15 + p] = o3;
    }
}

__device__ __forceinline__ void fft_phaseB_load(float2 (&u)[16],
                                                const float2* __restrict__ zbuf, int m)
{
    #pragma unroll
    for (int v = 0; v < 16; ++v) u[v] = zbuf[m + 21*v];
}

// Phase B: two radix-4 stages (Ns=20, Ns=80) in registers; write X natural.
__device__ __forceinline__ void fft_phaseB_compute(const float2 (&u)[16],
                                                   float2* __restrict__ xdst, int m)
{
    float s, c;
    sincospif((float)m * (1.0f/160.0f), &s, &c);
    float2 twm = make_float2(c, s);            // tw[m]
    float2 t2  = cmul(twm, twm);               // tw[2m]
    float2 tm3 = cmul(t2, twm);                // tw[3m]
    float2 t4  = cmul(t2, t2);                 // tw[4m]
    float2 w8  = cmul(t4, t4);                 // tw[8m]
    float2 w12 = cmul(w8, t4);                 // tw[12m]

    float2 t[4][4];
    #pragma unroll
    for (int cc = 0; cc < 4; ++cc) {
        radix4_bf(u[cc], u[cc+4], u[cc+8], u[cc+12], t4, w8, w12,
                  t[0][cc], t[1][cc], t[2][cc], t[3][cc]);
    }
    #pragma unroll
    for (int w = 0; w < 4; ++w) {
        float2 w1 = cmul(twm, cC20[w]);        // tw[m + 20w]
        float2 w2 = cmul(t2,  cD40[w]);        // tw[2m + 40w]
        float2 w3 = cmul(tm3, cE60[w]);        // tw[3m + 60w]
        float2 o0, o1, o2, o3;
        radix4_bf(t[w][0], t[w][1], t[w][2], t[w][3], w1, w2, w3, o0, o1, o2, o3);
        xdst[m + 20*w]       = o0;
        xdst[m + 20*w + 80]  = o1;
        xdst[m + 20*w + 160] = o2;
        xdst[m + 20*w + 240] = o3;
    }
}

// ===========================================================================
// Fused rows kernel: 16 grid rows/block, 320 threads (20 lanes/row),
// register FFT, dynamic smem (87 KB): sIn[18*RPITCH] | sA[16*RPITCH].
// z-buffer (16*ZPITCH = 5392) aliases sIn (18*321 = 5778).
// ===========================================================================
__global__ __launch_bounds__(320) void fused_rows_kernel(const float2* __restrict__ in)
{
    extern __shared__ float2 dyn[];
    float2* sIn = dyn;                    // 18 input rows, pitch 321
    float2* sA  = dyn + 18 * RPITCH;      // 16 grid rows -> FFT X, pitch 321
    int tid = threadIdx.x;
    int rl  = tid / 20;
    int m   = tid - rl * 20;
    int b   = blockIdx.x / 20;            // 20 = RESN/16
    int a0  = (blockIdx.x % 20) * 16;

    // grid rows 120..159 are identically zero (both vertical weights vanish)
    if (a0 == 128 || a0 == 144) {
        const float2 z = make_float2(0.f, 0.f);
        for (int i = tid; i < 16 * RESN; i += 320) {
            int n = i >> 4, ml = i & 15;
            g_tmp[((size_t)b * RESN + n) * RESN + a0 + ml] = z;
        }
        return;
    }

    const float2* cb = in + (size_t)b * HW;

    // 1. load 18 input rows (iy = a0-1 .. a0+16), zero-padded at edges
    for (int i = tid; i < 18 * RESN; i += 320) {
        int r = i / RESN, col = i - r * RESN;
        int iy = a0 - 1 + r;
        sIn[r * RPITCH + col] = (iy >= 0 && iy < RESN) ? __ldg(&cb[iy * RESN + col])
                                                       : make_float2(0.f, 0.f);
    }
    __syncthreads();

    // 2. 3x3 separable stencil -> grid rows in sA (natural order)
    int a = a0 + rl;
    float c0  = (a >= 120 && a <= 160) ? 0.f : 1.f;                              // jm(a)
    float c1  = (a + 1 <= 319 && !(a + 1 >= 120 && a + 1 <= 160)) ? 1.f : 0.f;   // jm(a+1)
    float c01 = c0 + c1;
    const float2* r0 = sIn + rl * RPITCH;   // iy = a-1
    const float2* r1 = r0 + RPITCH;         // iy = a
    const float2* r2 = r1 + RPITCH;         // iy = a+1
    float2* Arow = sA + rl * RPITCH;
    #pragma unroll
    for (int k = 0; k < 16; ++k) {
        int i = m + 20 * k;
        float w0 = (i >= 140 && i <= 170) ? 0.f : 1.f;                            // im(i)
        float w1 = (i + 1 <= 319 && !(i + 1 >= 140 && i + 1 <= 170)) ? 1.f : 0.f; // im(i+1)
        float cxc = w0 + w1;
        float vx, vy;
        {   // center column
            float2 A = r0[i], B = r1[i], C = r2[i];
            vx = cxc * (c0 * A.x + c01 * B.x + c1 * C.x);
            vy = cxc * (c0 * A.y + c01 * B.y + c1 * C.y);
        }
        if (i > 0) {
            float2 A = r0[i-1], B = r1[i-1], C = r2[i-1];
            vx += w0 * (c0 * A.x + c01 * B.x + c1 * C.x);
            vy += w0 * (c0 * A.y + c01 * B.y + c1 * C.y);
        }
        if (i < 319) {
            float2 A = r0[i+1], B = r1[i+1], C = r2[i+1];
            vx += w1 * (c0 * A.x + c01 * B.x + c1 * C.x);
            vy += w1 * (c0 * A.y + c01 * B.y + c1 * C.y);
        }
        if (a0 == 0 && rl == 0 && i == 0) {
            // all 21769 skipped trajectory points hit corner (0,0), weight 1/16
            float2 c00 = sIn[1 * RPITCH + 0];   // input row iy=0, col 0
            vx += 21769.f * c00.x;
            vy += 21769.f * c00.y;
        }
        float sgn = ((a + i) & 1) ? -0.0625f : 0.0625f;  // ifftshift pre-twist + 1/16
        Arow[i] = make_float2(vx * sgn, vy * sgn);
    }
    __syncthreads();   // all sIn reads done -> safe to alias as z-buffer; sA ready

    // 3. FFT phase A (16 of 20 lanes/row active): sA -> zbuf (aliases sIn)
    float2* zrow = dyn + rl * ZPITCH;
    if (m < 16) fft_phaseA(Arow, zrow, m);
    __syncthreads();

    // 4. FFT phase B: zbuf -> regs -> X into sA (distinct buffers, no mid-sync)
    float2 u[16];
    fft_phaseB_load(u, zrow, m);
    fft_phaseB_compute(u, Arow, m);
    __syncthreads();

    // 5. transposed store: g_tmp[b][n][a0+ml]
    for (int i = tid; i < 16 * RESN; i += 320) {
        int n  = i >> 4;
        int ml = i & 15;
        g_tmp[((size_t)b * RESN + n) * RESN + a0 + ml] = sA[ml * RPITCH + n];
    }
}

// ===========================================================================
// Column FFT kernel (measured-good R10/R14 config: 16 rows/block, 320 threads)
// ===========================================================================
__global__ __launch_bounds__(320) void fft_cols_kernel(float* __restrict__ out)
{
    __shared__ float2 buf[16 * ZPITCH];
    int tid = threadIdx.x;
    int rl  = tid / 20;
    int m   = tid - rl * 20;
    int rowg = blockIdx.x * 16 + rl;          // = b*320 + n
    const float2* src = g_tmp + (size_t)rowg * RESN;
    float2* brow = buf + rl * ZPITCH;

    // phase A: gmem -> registers -> z in smem
    if (m < 16) fft_phaseA(src, brow, m);
    __syncthreads();

    // phase B load (all of z consumed into regs before X overwrites buffer)
    float2 u[16];
    fft_phaseB_load(u, brow, m);
    __syncthreads();
    fft_phaseB_compute(u, brow, m);           // X natural order (0..319 < ZPITCH)
    __syncthreads();

    // store: fftshift post-twist (-1)^(q+n), planar real/imag
    int b  = (blockIdx.x * 16) / RESN;
    int n0 = (blockIdx.x * 16) % RESN;
    float* outb = out + (size_t)b * 2 * HW;
    for (int i = tid; i < 16 * RESN; i += 320) {
        int q  = i >> 4;    // image row (FFT output position)
        int nl = i & 15;    // column within this block's 16
        float2 v = buf[nl * ZPITCH + q];
        float sg = ((q + n0 + nl) & 1) ? -1.0f : 1.0f;
        outb[q * RESN + n0 + nl]      = v.x * sg;   // real plane
        outb[HW + q * RESN + n0 + nl] = v.y * sg;   // imag plane
    }
}

// ---------------------------------------------------------------------------
extern "C" void kernel_launch(void* const* d_in, const int* in_sizes, int n_in,
                              void* d_out, int out_size)
{
    const float2* in = (const float2*)d_in[0];   // k_space_input (B,1,320,320,2)
    float* out = (float*)d_out;                  // (B,1,2,320,320) float32
    (void)in_sizes; (void)n_in; (void)out_size;

    const int dyn_bytes = (18 * RPITCH + 16 * RPITCH) * (int)sizeof(float2);  // 87312
    cudaFuncSetAttribute(fused_rows_kernel,
                         cudaFuncAttributeMaxDynamicSharedMemorySize, dyn_bytes);

    fused_rows_kernel<<<BATCH * 20, 320, dyn_bytes>>>(in);
    fft_cols_kernel  <<<BATCH * 20, 320>>>(out);
}

// round 16
// speedup vs baseline: 1.1495x; 1.1495x over previous
#include <cuda_runtime.h>

#define RESN  320
#define BATCH 32
#define HW    (RESN*RESN)

#define LANES  80
#define NROWS  8
#define SPITCH 321   // float2 pitch for row-kernel smem
#define ZPITCH 337   // float2 pitch for cols-kernel z/X buffer

// Scratch (allocation-free rule: __device__ globals)
__device__ float2 g_tmp[BATCH*HW];   // intermediate after row FFTs, transposed

// ---------------------------------------------------------------------------
// complex helpers
// ---------------------------------------------------------------------------
__device__ __forceinline__ float2 cadd(float2 a, float2 b){ return make_float2(a.x+b.x, a.y+b.y); }
__device__ __forceinline__ float2 csub(float2 a, float2 b){ return make_float2(a.x-b.x, a.y-b.y); }
__device__ __forceinline__ float2 cmul(float2 a, float2 b){
    return make_float2(a.x*b.x - a.y*b.y, a.x*b.y + a.y*b.x);
}
__device__ __forceinline__ float2 cjmul(float2 a){ return make_float2(-a.y, a.x); } // i*a

// ===========================================================================
// Shared-twiddle Stockham FFT (used by the rows kernel, 80 lanes/row)
// ===========================================================================
__device__ __forceinline__ void build_twiddle(float2* tw, int tid, int nthreads)
{
    for (int k = tid; k < RESN; k += nthreads) {
        float s, c;
        sincospif(2.0f * (float)k / (float)RESN, &s, &c);
        tw[k] = make_float2(c, s);
    }
}

template<int Ns>
__device__ __forceinline__ void radix4_stage(const float2* __restrict__ src,
                                             float2* __restrict__ dst,
                                             const float2* __restrict__ tw, int j)
{
    float2 v0 = src[j];
    float2 v1 = src[j + 80];
    float2 v2 = src[j + 160];
    float2 v3 = src[j + 240];
    int m = j % Ns;
    constexpr int STEP = 80 / Ns;          // twiddle index step
    float2 w1 = tw[m * STEP];
    float2 w2 = cmul(w1, w1);
    float2 w3 = cmul(w2, w1);
    v1 = cmul(v1, w1);
    v2 = cmul(v2, w2);
    v3 = cmul(v3, w3);
    float2 t0 = cadd(v0, v2), t1 = csub(v0, v2);
    float2 t2 = cadd(v1, v3), t3 = csub(v1, v3);
    float2 it3 = cjmul(t3);
    int d = (j / Ns) * (4 * Ns) + m;
    dst[d]          = cadd(t0, t2);
    dst[d + Ns]     = cadd(t1, it3);
    dst[d + 2 * Ns] = csub(t0, t2);
    dst[d + 3 * Ns] = csub(t1, it3);
}

__device__ __forceinline__ void fft320_inv(float2* A, float2* B,
                                           const float2* tw, int lane)
{
    // stage 1: radix-5, Ns=1, 64 butterflies, no twiddle. A -> B
    if (lane < 64) {
        float2 v0 = A[lane], v1 = A[lane+64], v2 = A[lane+128],
               v3 = A[lane+192], v4 = A[lane+256];
        const float c1 =  0.30901699437494745f, c2 = -0.80901699437494745f;
        const float s1 =  0.95105651629515353f, s2 =  0.58778525229247314f;
        float2 t1 = cadd(v1, v4), t2 = cadd(v2, v3);
        float2 t3 = csub(v1, v4), t4 = csub(v2, v3);
        float2 a1 = make_float2(v0.x + c1*t1.x + c2*t2.x, v0.y + c1*t1.y + c2*t2.y);
        float2 a2 = make_float2(v0.x + c2*t1.x + c1*t2.x, v0.y + c2*t1.y + c1*t2.y);
        float2 b1 = make_float2(s1*t3.x + s2*t4.x, s1*t3.y + s2*t4.y);
        float2 b2 = make_float2(s2*t3.x - s1*t4.x, s2*t3.y - s1*t4.y);
        float2 ib1 = cjmul(b1), ib2 = cjmul(b2);
        int d = lane * 5;
        B[d + 0] = make_float2(v0.x + t1.x + t2.x, v0.y + t1.y + t2.y);
        B[d + 1] = cadd(a1, ib1);
        B[d + 2] = cadd(a2, ib2);
        B[d + 3] = csub(a2, ib2);
        B[d + 4] = csub(a1, ib1);
    }
    __syncthreads();
    radix4_stage<5 >(B, A, tw, lane);  __syncthreads();
    radix4_stage<20>(A, B, tw, lane);  __syncthreads();
    radix4_stage<80>(B, A, tw, lane);  __syncthreads();
    // result in A, natural order
}

// ===========================================================================
// Register FFT (20x16 decomposition, used by the cols kernel)
// ===========================================================================
__constant__ float2 cW20[13] = {   // exp(i*pi*j/10)
    { 1.f, 0.f},
    { 0.95105651629515353f, 0.30901699437494742f},
    { 0.80901699437494745f, 0.58778525229247314f},
    { 0.58778525229247314f, 0.80901699437494745f},
    { 0.30901699437494742f, 0.95105651629515353f},
    { 0.f, 1.f},
    {-0.30901699437494742f, 0.95105651629515353f},
    {-0.58778525229247314f, 0.80901699437494745f},
    {-0.80901699437494745f, 0.58778525229247314f},
    {-0.95105651629515353f, 0.30901699437494742f},
    {-1.f, 0.f},
    {-0.95105651629515353f, -0.30901699437494742f},
    {-0.80901699437494745f, -0.58778525229247314f}
};
__constant__ float2 cC20[4] = {    // exp(i*pi*w/8)
    {1.f,0.f},
    {0.92387953251128674f, 0.38268343236508978f},
    {0.70710678118654757f, 0.70710678118654757f},
    {0.38268343236508978f, 0.92387953251128674f}
};
__constant__ float2 cD40[4] = {    // exp(i*pi*w/4)
    {1.f,0.f},
    {0.70710678118654757f, 0.70710678118654757f},
    {0.f,1.f},
    {-0.70710678118654757f, 0.70710678118654757f}
};
__constant__ float2 cE60[4] = {    // exp(i*3*pi*w/8)
    {1.f,0.f},
    {0.38268343236508978f, 0.92387953251128674f},
    {-0.70710678118654757f, 0.70710678118654757f},
    {-0.92387953251128674f, -0.38268343236508978f}
};

__device__ __forceinline__ void radix5_bf(float2 v0, float2 v1, float2 v2, float2 v3, float2 v4,
                                          float2& o0, float2& o1, float2& o2, float2& o3, float2& o4)
{
    const float c1 =  0.30901699437494745f, c2 = -0.80901699437494745f;
    const float s1 =  0.95105651629515353f, s2 =  0.58778525229247314f;
    float2 t1 = cadd(v1, v4), t2 = cadd(v2, v3);
    float2 t3 = csub(v1, v4), t4 = csub(v2, v3);
    float2 a1 = make_float2(v0.x + c1*t1.x + c2*t2.x, v0.y + c1*t1.y + c2*t2.y);
    float2 a2 = make_float2(v0.x + c2*t1.x + c1*t2.x, v0.y + c2*t1.y + c1*t2.y);
    float2 b1 = make_float2(s1*t3.x + s2*t4.x, s1*t3.y + s2*t4.y);
    float2 b2 = make_float2(s2*t3.x - s1*t4.x, s2*t3.y - s1*t4.y);
    float2 ib1 = cjmul(b1), ib2 = cjmul(b2);
    o0 = make_float2(v0.x + t1.x + t2.x, v0.y + t1.y + t2.y);
    o1 = cadd(a1, ib1);
    o2 = cadd(a2, ib2);
    o3 = csub(a2, ib2);
    o4 = csub(a1, ib1);
}

__device__ __forceinline__ void radix4_bf(float2 v0, float2 v1, float2 v2, float2 v3,
                                          float2 w1, float2 w2, float2 w3,
                                          float2& o0, float2& o1, float2& o2, float2& o3)
{
    v1 = cmul(v1, w1); v2 = cmul(v2, w2); v3 = cmul(v3, w3);
    float2 t0 = cadd(v0, v2), t1 = csub(v0, v2);
    float2 t2 = cadd(v1, v3), t3 = csub(v1, v3);
    float2 it3 = cjmul(t3);
    o0 = cadd(t0, t2); o1 = cadd(t1, it3); o2 = csub(t0, t2); o3 = csub(t1, it3);
}

// Phase A: radix-5 then radix-4 (Ns=1, Ns=5) in registers; thread g = 0..15.
__device__ __forceinline__ void fft_phaseA(const float2* __restrict__ src,
                                           float2* __restrict__ zbuf, int g)
{
    float2 f[4][5];
    #pragma unroll
    for (int k = 0; k < 4; ++k) {
        float2 e0 = src[g + 16*k];
        float2 e1 = src[g + 16*k + 64];
        float2 e2 = src[g + 16*k + 128];
        float2 e3 = src[g + 16*k + 192];
        float2 e4 = src[g + 16*k + 256];
        radix5_bf(e0, e1, e2, e3, e4,
                  f[k][0], f[k][1], f[k][2], f[k][3], f[k][4]);
    }
    #pragma unroll
    for (int p = 0; p < 5; ++p) {
        float2 o0, o1, o2, o3;
        radix4_bf(f[0][p], f[1][p], f[2][p], f[3][p],
                  cW20[p], cW20[2*p], cW20[3*p], o0, o1, o2, o3);
        zbuf[21*g + p]      = o0;
        zbuf[21*g + 5 + p]  = o1;
        zbuf[21*g + 10 + p] = o2;
        zbuf[21*g + 15 + p] = o3;
    }
}

__device__ __forceinline__ void fft_phaseB_load(float2 (&u)[16],
                                                const float2* __restrict__ zbuf, int m)
{
    #pragma unroll
    for (int v = 0; v < 16; ++v) u[v] = zbuf[m + 21*v];
}

// Phase B: two radix-4 stages (Ns=20, Ns=80) in registers; write X natural.
__device__ __forceinline__ void fft_phaseB_compute(const float2 (&u)[16],
                                                   float2* __restrict__ xdst, int m)
{
    float s, c;
    sincospif((float)m * (1.0f/160.0f), &s, &c);
    float2 twm = make_float2(c, s);            // tw[m]
    float2 t2  = cmul(twm, twm);               // tw[2m]
    float2 tm3 = cmul(t2, twm);                // tw[3m]
    float2 t4  = cmul(t2, t2);                 // tw[4m]
    float2 w8  = cmul(t4, t4);                 // tw[8m]
    float2 w12 = cmul(w8, t4);                 // tw[12m]

    float2 t[4][4];
    #pragma unroll
    for (int cc = 0; cc < 4; ++cc) {
        radix4_bf(u[cc], u[cc+4], u[cc+8], u[cc+12], t4, w8, w12,
                  t[0][cc], t[1][cc], t[2][cc], t[3][cc]);
    }
    #pragma unroll
    for (int w = 0; w < 4; ++w) {
        float2 w1 = cmul(twm, cC20[w]);        // tw[m + 20w]
        float2 w2 = cmul(t2,  cD40[w]);        // tw[2m + 40w]
        float2 w3 = cmul(tm3, cE60[w]);        // tw[3m + 60w]
        float2 o0, o1, o2, o3;
        radix4_bf(t[w][0], t[w][1], t[w][2], t[w][3], w1, w2, w3, o0, o1, o2, o3);
        xdst[m + 20*w]       = o0;
        xdst[m + 20*w + 80]  = o1;
        xdst[m + 20*w + 160] = o2;
        xdst[m + 20*w + 240] = o3;
    }
}

// ===========================================================================
// Fused rows kernel (measured-good R14 config: 640 threads, 80 lanes/row,
// smem Stockham) with zero-block skip for grid rows 120..159.
// ===========================================================================
__global__ __launch_bounds__(NROWS*LANES) void fused_rows_kernel(const float2* __restrict__ in)
{
    __shared__ float2 sA[NROWS * SPITCH];   // rowcomb -> grid rows -> FFT in/out
    __shared__ float2 sB[10 * SPITCH];      // input rows, later FFT scratch
    __shared__ float2 sTw[RESN];            // twiddle table
    int tid  = threadIdx.x;
    int rl   = tid / LANES;
    int lane = tid - rl * LANES;
    int b  = blockIdx.x / (RESN / NROWS);
    int a0 = (blockIdx.x % (RESN / NROWS)) * NROWS;

    // grid rows 120..159 are identically zero: jm(a)=0 for a in [120,160] and
    // jm(a+1)=0 for a in [119,159] -> both vanish on [120,159]. Blocks
    // a0 in {120,128,136,144,152} cover exactly those rows: store zeros, done.
    if (a0 >= 120 && a0 <= 152) {
        const float2 z = make_float2(0.f, 0.f);
        for (int i = tid; i < NROWS * RESN; i += NROWS * LANES) {
            int n = i >> 3, ml = i & 7;
            g_tmp[((size_t)b * RESN + n) * RESN + a0 + ml] = z;
        }
        return;
    }

    const float2* cb = in + (size_t)b * HW;

    build_twiddle(sTw, tid, NROWS * LANES);

    // 1. load 10 input rows (iy = a0-1 .. a0+8), zero-padded at edges
    for (int i = tid; i < 10 * RESN; i += NROWS * LANES) {
        int r = i / RESN, col = i - r * RESN;
        int iy = a0 - 1 + r;
        float2 v = (iy >= 0 && iy < RESN) ? __ldg(&cb[iy * RESN + col])
                                          : make_float2(0.f, 0.f);
        sB[r * SPITCH + col] = v;
    }
    __syncthreads();

    // 2. vertical pass
    int a = a0 + rl;
    float c0 = (a >= 120 && a <= 160) ? 0.f : 1.f;                            // jm(a)
    float c1 = (a + 1 <= 319 && !(a + 1 >= 120 && a + 1 <= 160)) ? 1.f : 0.f; // jm(a+1)
    float c01 = c0 + c1;
    const float2* r0 = sB + rl * SPITCH;        // iy = a-1
    const float2* r1 = r0 + SPITCH;             // iy = a
    const float2* r2 = r1 + SPITCH;             // iy = a+1
    float2* A = sA + rl * SPITCH;
    #pragma unroll
    for (int k = 0; k < 4; ++k) {
        int i = lane + 80 * k;
        float2 v;
        v.x = c0 * r0[i].x + c01 * r1[i].x + c1 * r2[i].x;
        v.y = c0 * r0[i].y + c01 * r1[i].y + c1 * r2[i].y;
        A[i] = v;
    }
    __syncthreads();

    // 3. horizontal pass (regs, sync, write back)
    float2 vals[4];
    #pragma unroll
    for (int k = 0; k < 4; ++k) {
        int bx = lane + 80 * k;
        float2 rc  = A[bx];
        float2 rcm = (bx > 0)   ? A[bx - 1] : make_float2(0.f, 0.f);
        float2 rcp = (bx < 319) ? A[bx + 1] : make_float2(0.f, 0.f);
        float w0 = (bx >= 140 && bx <= 170) ? 0.f : 1.f;                      // im(bx)
        float w1 = (bx + 1 <= 319 && !(bx + 1 >= 140 && bx + 1 <= 170)) ? 1.f : 0.f;
        float vx = w0 * (rcm.x + rc.x) + w1 * (rc.x + rcp.x);
        float vy = w0 * (rcm.y + rc.y) + w1 * (rc.y + rcp.y);
        if (a0 == 0 && rl == 0 && bx == 0) {
            // all 21769 skipped trajectory points hit corner (0,0), weight 1/16
            float2 c00 = sB[1 * SPITCH + 0];   // input row iy=0, col 0
            vx += 21769.f * c00.x;
            vy += 21769.f * c00.y;
        }
        float s = ((a + bx) & 1) ? -0.0625f : 0.0625f;   // ifftshift pre-twist + 1/16
        vals[k] = make_float2(vx * s, vy * s);
    }
    __syncthreads();
    #pragma unroll
    for (int k = 0; k < 4; ++k) A[lane + 80 * k] = vals[k];
    __syncthreads();

    // 4. row FFT (sB rows reused as scratch)
    fft320_inv(A, sB + rl * SPITCH, sTw, lane);

    // 5. transposed store: g_tmp[b][n][a0+ml]
    for (int i = tid; i < NROWS * RESN; i += NROWS * LANES) {
        int n  = i >> 3;
        int ml = i & 7;
        g_tmp[((size_t)b * RESN + n) * RESN + a0 + ml] = sA[ml * SPITCH + n];
    }
}

// ===========================================================================
// Column FFT kernel (measured-good R10/R14 config: 16 rows/block, 320 threads)
// ===========================================================================
__global__ __launch_bounds__(320) void fft_cols_kernel(float* __restrict__ out)
{
    __shared__ float2 buf[16 * ZPITCH];
    int tid = threadIdx.x;
    int rl  = tid / 20;
    int m   = tid - rl * 20;
    int rowg = blockIdx.x * 16 + rl;          // = b*320 + n
    const float2* src = g_tmp + (size_t)rowg * RESN;
    float2* brow = buf + rl * ZPITCH;

    // phase A: gmem -> registers -> z in smem
    if (m < 16) fft_phaseA(src, brow, m);
    __syncthreads();

    // phase B load (all of z consumed into regs before X overwrites buffer)
    float2 u[16];
    fft_phaseB_load(u, brow, m);
    __syncthreads();
    fft_phaseB_compute(u, brow, m);           // X natural order (0..319 < ZPITCH)
    __syncthreads();

    // store: fftshift post-twist (-1)^(q+n), planar real/imag
    int b  = (blockIdx.x * 16) / RESN;
    int n0 = (blockIdx.x * 16) % RESN;
    float* outb = out + (size_t)b * 2 * HW;
    for (int i = tid; i < 16 * RESN; i += 320) {
        int q  = i >> 4;    // image row (FFT output position)
        int nl = i & 15;    // column within this block's 16
        float2 v = buf[nl * ZPITCH + q];
        float sg = ((q + n0 + nl) & 1) ? -1.0f : 1.0f;
        outb[q * RESN + n0 + nl]      = v.x * sg;   // real plane
        outb[HW + q * RESN + n0 + nl] = v.y * sg;   // imag plane
    }
}

// ---------------------------------------------------------------------------
extern "C" void kernel_launch(void* const* d_in, const int* in_sizes, int n_in,
                              void* d_out, int out_size)
{
    const float2* in = (const float2*)d_in[0];   // k_space_input (B,1,320,320,2)
    float* out = (float*)d_out;                  // (B,1,2,320,320) float32
    (void)in_sizes; (void)n_in; (void)out_size;

    fused_rows_kernel<<<BATCH * (RESN / NROWS), NROWS * LANES>>>(in);
    fft_cols_kernel  <<<BATCH * (RESN / 16), 320>>>(out);
}

// round 17
// speedup vs baseline: 1.1917x; 1.0366x over previous
#include <cuda_runtime.h>

#define RESN  320
#define BATCH 32
#define HW    (RESN*RESN)

#define LANES  80
#define NROWS  8
#define SPITCH 321   // float2 pitch for row-kernel smem
#define ZPITCH 337   // float2 pitch for cols-kernel z/X buffer

// Scratch (allocation-free rule: __device__ globals)
__device__ float2 g_tmp[BATCH*HW];   // intermediate after row FFTs, transposed

// ---------------------------------------------------------------------------
// complex helpers
// ---------------------------------------------------------------------------
__device__ __forceinline__ float2 cadd(float2 a, float2 b){ return make_float2(a.x+b.x, a.y+b.y); }
__device__ __forceinline__ float2 csub(float2 a, float2 b){ return make_float2(a.x-b.x, a.y-b.y); }
__device__ __forceinline__ float2 cmul(float2 a, float2 b){
    return make_float2(a.x*b.x - a.y*b.y, a.x*b.y + a.y*b.x);
}
__device__ __forceinline__ float2 cjmul(float2 a){ return make_float2(-a.y, a.x); } // i*a

// ===========================================================================
// Shared-twiddle Stockham machinery (rows kernel, 80 lanes/row)
// ===========================================================================
__device__ __forceinline__ void build_twiddle(float2* tw, int tid, int nthreads)
{
    for (int k = tid; k < RESN; k += nthreads) {
        float s, c;
        sincospif(2.0f * (float)k / (float)RESN, &s, &c);
        tw[k] = make_float2(c, s);
    }
}

template<int Ns>
__device__ __forceinline__ void radix4_stage(const float2* __restrict__ src,
                                             float2* __restrict__ dst,
                                             const float2* __restrict__ tw, int j)
{
    float2 v0 = src[j];
    float2 v1 = src[j + 80];
    float2 v2 = src[j + 160];
    float2 v3 = src[j + 240];
    int m = j % Ns;
    constexpr int STEP = 80 / Ns;          // twiddle index step
    float2 w1 = tw[m * STEP];
    float2 w2 = cmul(w1, w1);
    float2 w3 = cmul(w2, w1);
    v1 = cmul(v1, w1);
    v2 = cmul(v2, w2);
    v3 = cmul(v3, w3);
    float2 t0 = cadd(v0, v2), t1 = csub(v0, v2);
    float2 t2 = cadd(v1, v3), t3 = csub(v1, v3);
    float2 it3 = cjmul(t3);
    int d = (j / Ns) * (4 * Ns) + m;
    dst[d]          = cadd(t0, t2);
    dst[d + Ns]     = cadd(t1, it3);
    dst[d + 2 * Ns] = csub(t0, t2);
    dst[d + 3 * Ns] = csub(t1, it3);
}

__device__ __forceinline__ void radix5_bf(float2 v0, float2 v1, float2 v2, float2 v3, float2 v4,
                                          float2& o0, float2& o1, float2& o2, float2& o3, float2& o4)
{
    const float c1 =  0.30901699437494745f, c2 = -0.80901699437494745f;
    const float s1 =  0.95105651629515353f, s2 =  0.58778525229247314f;
    float2 t1 = cadd(v1, v4), t2 = cadd(v2, v3);
    float2 t3 = csub(v1, v4), t4 = csub(v2, v3);
    float2 a1 = make_float2(v0.x + c1*t1.x + c2*t2.x, v0.y + c1*t1.y + c2*t2.y);
    float2 a2 = make_float2(v0.x + c2*t1.x + c1*t2.x, v0.y + c2*t1.y + c1*t2.y);
    float2 b1 = make_float2(s1*t3.x + s2*t4.x, s1*t3.y + s2*t4.y);
    float2 b2 = make_float2(s2*t3.x - s1*t4.x, s2*t3.y - s1*t4.y);
    float2 ib1 = cjmul(b1), ib2 = cjmul(b2);
    o0 = make_float2(v0.x + t1.x + t2.x, v0.y + t1.y + t2.y);
    o1 = cadd(a1, ib1);
    o2 = cadd(a2, ib2);
    o3 = csub(a2, ib2);
    o4 = csub(a1, ib1);
}

// ===========================================================================
// Register FFT constants (cols kernel, 20x16 decomposition)
// ===========================================================================
__constant__ float2 cW20[13] = {   // exp(i*pi*j/10)
    { 1.f, 0.f},
    { 0.95105651629515353f, 0.30901699437494742f},
    { 0.80901699437494745f, 0.58778525229247314f},
    { 0.58778525229247314f, 0.80901699437494745f},
    { 0.30901699437494742f, 0.95105651629515353f},
    { 0.f, 1.f},
    {-0.30901699437494742f, 0.95105651629515353f},
    {-0.58778525229247314f, 0.80901699437494745f},
    {-0.80901699437494745f, 0.58778525229247314f},
    {-0.95105651629515353f, 0.30901699437494742f},
    {-1.f, 0.f},
    {-0.95105651629515353f, -0.30901699437494742f},
    {-0.80901699437494745f, -0.58778525229247314f}
};
__constant__ float2 cC20[4] = {    // exp(i*pi*w/8)
    {1.f,0.f},
    {0.92387953251128674f, 0.38268343236508978f},
    {0.70710678118654757f, 0.70710678118654757f},
    {0.38268343236508978f, 0.92387953251128674f}
};
__constant__ float2 cD40[4] = {    // exp(i*pi*w/4)
    {1.f,0.f},
    {0.70710678118654757f, 0.70710678118654757f},
    {0.f,1.f},
    {-0.70710678118654757f, 0.70710678118654757f}
};
__constant__ float2 cE60[4] = {    // exp(i*3*pi*w/8)
    {1.f,0.f},
    {0.38268343236508978f, 0.92387953251128674f},
    {-0.70710678118654757f, 0.70710678118654757f},
    {-0.92387953251128674f, -0.38268343236508978f}
};

__device__ __forceinline__ void radix4_bf(float2 v0, float2 v1, float2 v2, float2 v3,
                                          float2 w1, float2 w2, float2 w3,
                                          float2& o0, float2& o1, float2& o2, float2& o3)
{
    v1 = cmul(v1, w1); v2 = cmul(v2, w2); v3 = cmul(v3, w3);
    float2 t0 = cadd(v0, v2), t1 = csub(v0, v2);
    float2 t2 = cadd(v1, v3), t3 = csub(v1, v3);
    float2 it3 = cjmul(t3);
    o0 = cadd(t0, t2); o1 = cadd(t1, it3); o2 = csub(t0, t2); o3 = csub(t1, it3);
}

// Phase A: radix-5 then radix-4 (Ns=1, Ns=5) in registers; thread g = 0..15.
__device__ __forceinline__ void fft_phaseA(const float2* __restrict__ src,
                                           float2* __restrict__ zbuf, int g)
{
    float2 f[4][5];
    #pragma unroll
    for (int k = 0; k < 4; ++k) {
        float2 e0 = src[g + 16*k];
        float2 e1 = src[g + 16*k + 64];
        float2 e2 = src[g + 16*k + 128];
        float2 e3 = src[g + 16*k + 192];
        float2 e4 = src[g + 16*k + 256];
        radix5_bf(e0, e1, e2, e3, e4,
                  f[k][0], f[k][1], f[k][2], f[k][3], f[k][4]);
    }
    #pragma unroll
    for (int p = 0; p < 5; ++p) {
        float2 o0, o1, o2, o3;
        radix4_bf(f[0][p], f[1][p], f[2][p], f[3][p],
                  cW20[p], cW20[2*p], cW20[3*p], o0, o1, o2, o3);
        zbuf[21*g + p]      = o0;
        zbuf[21*g + 5 + p]  = o1;
        zbuf[21*g + 10 + p] = o2;
        zbuf[21*g + 15 + p] = o3;
    }
}

__device__ __forceinline__ void fft_phaseB_load(float2 (&u)[16],
                                                const float2* __restrict__ zbuf, int m)
{
    #pragma unroll
    for (int v = 0; v < 16; ++v) u[v] = zbuf[m + 21*v];
}

// Phase B: two radix-4 stages (Ns=20, Ns=80) in registers; write X natural.
__device__ __forceinline__ void fft_phaseB_compute(const float2 (&u)[16],
                                                   float2* __restrict__ xdst, int m)
{
    float s, c;
    sincospif((float)m * (1.0f/160.0f), &s, &c);
    float2 twm = make_float2(c, s);            // tw[m]
    float2 t2  = cmul(twm, twm);               // tw[2m]
    float2 tm3 = cmul(t2, twm);                // tw[3m]
    float2 t4  = cmul(t2, t2);                 // tw[4m]
    float2 w8  = cmul(t4, t4);                 // tw[8m]
    float2 w12 = cmul(w8, t4);                 // tw[12m]

    float2 t[4][4];
    #pragma unroll
    for (int cc = 0; cc < 4; ++cc) {
        radix4_bf(u[cc], u[cc+4], u[cc+8], u[cc+12], t4, w8, w12,
                  t[0][cc], t[1][cc], t[2][cc], t[3][cc]);
    }
    #pragma unroll
    for (int w = 0; w < 4; ++w) {
        float2 w1 = cmul(twm, cC20[w]);        // tw[m + 20w]
        float2 w2 = cmul(t2,  cD40[w]);        // tw[2m + 40w]
        float2 w3 = cmul(tm3, cE60[w]);        // tw[3m + 60w]
        float2 o0, o1, o2, o3;
        radix4_bf(t[w][0], t[w][1], t[w][2], t[w][3], w1, w2, w3, o0, o1, o2, o3);
        xdst[m + 20*w]       = o0;
        xdst[m + 20*w + 80]  = o1;
        xdst[m + 20*w + 160] = o2;
        xdst[m + 20*w + 240] = o3;
    }
}

// ===========================================================================
// Fused rows kernel: 640 threads, 80 lanes/row, smem Stockham.
// Horizontal stencil folded into the radix-5 load; zero-block skip for
// grid rows 120..159.
// ===========================================================================
__global__ __launch_bounds__(NROWS*LANES) void fused_rows_kernel(const float2* __restrict__ in)
{
    __shared__ float2 sA[NROWS * SPITCH];   // rowcomb -> FFT ping buffer
    __shared__ float2 sB[10 * SPITCH];      // input rows, later FFT scratch
    __shared__ float2 sTw[RESN];            // twiddle table
    int tid  = threadIdx.x;
    int rl   = tid / LANES;
    int lane = tid - rl * LANES;
    int b  = blockIdx.x / (RESN / NROWS);
    int a0 = (blockIdx.x % (RESN / NROWS)) * NROWS;

    // grid rows 120..159 are identically zero (both vertical weights vanish):
    // blocks a0 in {120,128,136,144,152}: store zeros, done.
    if (a0 >= 120 && a0 <= 152) {
        const float2 z = make_float2(0.f, 0.f);
        for (int i = tid; i < NROWS * RESN; i += NROWS * LANES) {
            int n = i >> 3, ml = i & 7;
            g_tmp[((size_t)b * RESN + n) * RESN + a0 + ml] = z;
        }
        return;
    }

    const float2* cb = in + (size_t)b * HW;

    build_twiddle(sTw, tid, NROWS * LANES);

    // 1. load 10 input rows (iy = a0-1 .. a0+8), zero-padded at edges
    for (int i = tid; i < 10 * RESN; i += NROWS * LANES) {
        int r = i / RESN, col = i - r * RESN;
        int iy = a0 - 1 + r;
        float2 v = (iy >= 0 && iy < RESN) ? __ldg(&cb[iy * RESN + col])
                                          : make_float2(0.f, 0.f);
        sB[r * SPITCH + col] = v;
    }
    __syncthreads();

    // corner term (read BEFORE sB is reused as FFT scratch): all 21769 skipped
    // trajectory points hit grid (0,0) with weight 1/16.
    float2 corner = make_float2(0.f, 0.f);
    if (a0 == 0 && rl == 0) {
        float2 c00 = sB[1 * SPITCH + 0];   // input row iy=0, col 0
        corner = make_float2(21769.f * c00.x, 21769.f * c00.y);
    }

    // 2. vertical pass: rowcomb into sA
    int a = a0 + rl;
    float c0 = (a >= 120 && a <= 160) ? 0.f : 1.f;                            // jm(a)
    float c1 = (a + 1 <= 319 && !(a + 1 >= 120 && a + 1 <= 160)) ? 1.f : 0.f; // jm(a+1)
    float c01 = c0 + c1;
    const float2* r0 = sB + rl * SPITCH;        // iy = a-1
    const float2* r1 = r0 + SPITCH;             // iy = a
    const float2* r2 = r1 + SPITCH;             // iy = a+1
    float2* A = sA + rl * SPITCH;
    #pragma unroll
    for (int k = 0; k < 4; ++k) {
        int i = lane + 80 * k;
        float2 v;
        v.x = c0 * r0[i].x + c01 * r1[i].x + c1 * r2[i].x;
        v.y = c0 * r0[i].y + c01 * r1[i].y + c1 * r2[i].y;
        A[i] = v;
    }
    __syncthreads();

    // 3. radix-5 stage with the horizontal stencil folded into the load.
    //    grid(e) = sgn(e)/16 * [ (w0+w1)*rc[e] + w0*rc[e-1] + w1*rc[e+1] ] (+corner at e=0)
    float2* B = sB + rl * SPITCH;
    if (lane < 64) {
        float2 g[5];
        #pragma unroll
        for (int s5 = 0; s5 < 5; ++s5) {
            int e = lane + 64 * s5;
            float w0 = (e >= 140 && e <= 170) ? 0.f : 1.f;                        // im(e)
            float w1 = (e < 319 && !(e + 1 >= 140 && e + 1 <= 170)) ? 1.f : 0.f;  // im(e+1)
            float2 rc = A[e];
            float vx = (w0 + w1) * rc.x;
            float vy = (w0 + w1) * rc.y;
            if (e > 0)   { float2 t = A[e-1]; vx += w0 * t.x; vy += w0 * t.y; }
            if (e < 319) { float2 t = A[e+1]; vx += w1 * t.x; vy += w1 * t.y; }
            if (e == 0)  { vx += corner.x;    vy += corner.y; }
            float sgn = ((a + e) & 1) ? -0.0625f : 0.0625f;   // ifftshift pre-twist + 1/16
            g[s5] = make_float2(vx * sgn, vy * sgn);
        }
        float2 o0, o1, o2, o3, o4;
        radix5_bf(g[0], g[1], g[2], g[3], g[4], o0, o1, o2, o3, o4);
        int d = lane * 5;
        B[d + 0] = o0; B[d + 1] = o1; B[d + 2] = o2; B[d + 3] = o3; B[d + 4] = o4;
    }
    __syncthreads();

    // 4. remaining radix-4 stages (result natural order in sA)
    radix4_stage<5 >(B, A, sTw, lane);  __syncthreads();
    radix4_stage<20>(A, B, sTw, lane);  __syncthreads();
    radix4_stage<80>(B, A, sTw, lane);  __syncthreads();

    // 5. transposed store: g_tmp[b][n][a0+ml]
    for (int i = tid; i < NROWS * RESN; i += NROWS * LANES) {
        int n  = i >> 3;
        int ml = i & 7;
        g_tmp[((size_t)b * RESN + n) * RESN + a0 + ml] = sA[ml * SPITCH + n];
    }
}

// ===========================================================================
// Column FFT kernel: register FFT, 16 rows/block, 320 threads,
// min 4 blocks/SM to lift occupancy (regs were the limiter at 60).
// ===========================================================================
__global__ __launch_bounds__(320, 4) void fft_cols_kernel(float* __restrict__ out)
{
    __shared__ float2 buf[16 * ZPITCH];
    int tid = threadIdx.x;
    int rl  = tid / 20;
    int m   = tid - rl * 20;
    int rowg = blockIdx.x * 16 + rl;          // = b*320 + n
    const float2* src = g_tmp + (size_t)rowg * RESN;
    float2* brow = buf + rl * ZPITCH;

    // phase A: gmem -> registers -> z in smem
    if (m < 16) fft_phaseA(src, brow, m);
    __syncthreads();

    // phase B load (all of z consumed into regs before X overwrites buffer)
    float2 u[16];
    fft_phaseB_load(u, brow, m);
    __syncthreads();
    fft_phaseB_compute(u, brow, m);           // X natural order (0..319 < ZPITCH)
    __syncthreads();

    // store: fftshift post-twist (-1)^(q+n), planar real/imag
    int b  = (blockIdx.x * 16) / RESN;
    int n0 = (blockIdx.x * 16) % RESN;
    float* outb = out + (size_t)b * 2 * HW;
    for (int i = tid; i < 16 * RESN; i += 320) {
        int q  = i >> 4;    // image row (FFT output position)
        int nl = i & 15;    // column within this block's 16
        float2 v = buf[nl * ZPITCH + q];
        float sg = ((q + n0 + nl) & 1) ? -1.0f : 1.0f;
        outb[q * RESN + n0 + nl]      = v.x * sg;   // real plane
        outb[HW + q * RESN + n0 + nl] = v.y * sg;   // imag plane
    }
}

// ---------------------------------------------------------------------------
extern "C" void kernel_launch(void* const* d_in, const int* in_sizes, int n_in,
                              void* d_out, int out_size)
{
    const float2* in = (const float2*)d_in[0];   // k_space_input (B,1,320,320,2)
    float* out = (float*)d_out;                  // (B,1,2,320,320) float32
    (void)in_sizes; (void)n_in; (void)out_size;

    fused_rows_kernel<<<BATCH * (RESN / NROWS), NROWS * LANES>>>(in);
    fft_cols_kernel  <<<BATCH * (RESN / 16), 320>>>(out);
}